// round 3
// baseline (speedup 1.0000x reference)
#include <cuda_runtime.h>
#include <cstdint>

#define N_NODES 100000
#define N_EDGES 1200000
#define D_FEAT  64
#define NBLK    ((N_NODES + 255) / 256)   // 391 scan blocks

// THETA = (1.0, -0.8, 0.4, -0.1)
#define THETA0  1.0f

// ---------------- scratch (static device memory; no allocs allowed) --------
__device__ int   g_deg  [N_NODES];
__device__ int   g_cur  [N_NODES];
__device__ int   g_offs [N_NODES];
__device__ int   g_bsum [512];
__device__ int   g_bbase[512];
__device__ float g_dinv [N_NODES];
__device__ int2  g_csr  [N_EDGES];                       // {src<<4, bits(dinv[src])}
__device__ float g_featA[(size_t)N_NODES * D_FEAT];
__device__ float g_featB[(size_t)N_NODES * D_FEAT];

// ---------------- preprocessing kernels ------------------------------------

__global__ void zero_kernel() {
    int v = blockIdx.x * blockDim.x + threadIdx.x;
    if (v < N_NODES) { g_deg[v] = 0; g_cur[v] = 0; }
}

__global__ void deg_kernel(const int* __restrict__ dst) {
    int e = blockIdx.x * blockDim.x + threadIdx.x;
    if (e < N_EDGES) atomicAdd(&g_deg[__ldg(dst + e)], 1);
}

__global__ void dinv_kernel() {
    int v = blockIdx.x * blockDim.x + threadIdx.x;
    if (v < N_NODES) {
        float d = (float)g_deg[v];
        g_dinv[v] = rsqrtf(fmaxf(d, 1.0f));
    }
}

// Phase A: per-block exclusive scan of deg, emit block sums.
__global__ void scan_blocks() {
    __shared__ int sh[256];
    int tid = threadIdx.x;
    int v = blockIdx.x * 256 + tid;
    int d = (v < N_NODES) ? g_deg[v] : 0;
    sh[tid] = d;
    __syncthreads();
    #pragma unroll
    for (int off = 1; off < 256; off <<= 1) {
        int t = (tid >= off) ? sh[tid - off] : 0;
        __syncthreads();
        sh[tid] += t;
        __syncthreads();
    }
    if (v < N_NODES) g_offs[v] = sh[tid] - d;   // exclusive within block
    if (tid == 255) g_bsum[blockIdx.x] = sh[255];
}

// Phase B: scan the 391 block sums (single block).
__global__ void scan_sums() {
    __shared__ int sh[512];
    int tid = threadIdx.x;
    int d = (tid < NBLK) ? g_bsum[tid] : 0;
    sh[tid] = d;
    __syncthreads();
    #pragma unroll
    for (int off = 1; off < 512; off <<= 1) {
        int t = (tid >= off) ? sh[tid - off] : 0;
        __syncthreads();
        sh[tid] += t;
        __syncthreads();
    }
    g_bbase[tid] = sh[tid] - d;                 // exclusive
}

// Phase C: add block bases.
__global__ void add_base() {
    int v = blockIdx.x * blockDim.x + threadIdx.x;
    if (v < N_NODES) g_offs[v] += g_bbase[v >> 8];
}

// Fill CSR buckets: entry = {src<<4, bits(dinv[src])}.
__global__ void fill_kernel(const int* __restrict__ src, const int* __restrict__ dst) {
    int e = blockIdx.x * blockDim.x + threadIdx.x;
    if (e >= N_EDGES) return;
    int d = __ldg(dst + e);
    int s = __ldg(src + e);
    int pos = g_offs[d] + atomicAdd(&g_cur[d], 1);
    g_csr[pos] = make_int2(s << 4, __float_as_int(g_dinv[s]));
}

// ---------------- fused gather + node update --------------------------------
// 16 threads per node (one float4 lane each).
//   acc = sum over in-edges of feat[src]*dinv[src]   (registers, no atomics)
//   fnew = feat[v] - acc*dinv[v]
//   out  = first ? THETA0*fold + theta*fnew : out + theta*fnew
__global__ void agg_update_kernel(const float4* __restrict__ fin,
                                  float4* __restrict__ fout,
                                  float4* __restrict__ out,
                                  float theta, int first, int write_feat) {
    int gid = blockIdx.x * blockDim.x + threadIdx.x;
    int v = gid >> 4;
    if (v >= N_NODES) return;
    int c = gid & 15;

    int beg = g_offs[v];
    int end = beg + g_deg[v];

    float ax = 0.f, ay = 0.f, az = 0.f, aw = 0.f;
    int i = beg;
    // unroll-2 for memory-level parallelism
    for (; i + 2 <= end; i += 2) {
        int2 e0 = __ldg(&g_csr[i]);
        int2 e1 = __ldg(&g_csr[i + 1]);
        float4 f0 = __ldg(fin + e0.x + c);
        float4 f1 = __ldg(fin + e1.x + c);
        float d0 = __int_as_float(e0.y);
        float d1 = __int_as_float(e1.y);
        ax += f0.x * d0 + f1.x * d1;
        ay += f0.y * d0 + f1.y * d1;
        az += f0.z * d0 + f1.z * d1;
        aw += f0.w * d0 + f1.w * d1;
    }
    if (i < end) {
        int2 e0 = __ldg(&g_csr[i]);
        float4 f0 = __ldg(fin + e0.x + c);
        float d0 = __int_as_float(e0.y);
        ax += f0.x * d0;
        ay += f0.y * d0;
        az += f0.z * d0;
        aw += f0.w * d0;
    }

    float dv = __ldg(&g_dinv[v]);
    float4 f = __ldg(fin + v * 16 + c);
    float fx = f.x - ax * dv;
    float fy = f.y - ay * dv;
    float fz = f.z - az * dv;
    float fw = f.w - aw * dv;

    if (write_feat) fout[v * 16 + c] = make_float4(fx, fy, fz, fw);

    int oi = v * 16 + c;
    if (first) {
        out[oi] = make_float4(THETA0 * f.x + theta * fx,
                              THETA0 * f.y + theta * fy,
                              THETA0 * f.z + theta * fz,
                              THETA0 * f.w + theta * fw);
    } else {
        float4 o = out[oi];
        out[oi] = make_float4(o.x + theta * fx, o.y + theta * fy,
                              o.z + theta * fz, o.w + theta * fw);
    }
}

// ---------------- launch -----------------------------------------------------

extern "C" void kernel_launch(void* const* d_in, const int* in_sizes, int n_in,
                              void* d_out, int out_size) {
    const float* feat = (const float*)d_in[0];
    const int*   src  = (const int*)d_in[1];
    const int*   dst  = (const int*)d_in[2];
    float4* out = (float4*)d_out;

    const int T = 256;
    zero_kernel<<<(N_NODES + T - 1) / T, T>>>();
    deg_kernel <<<(N_EDGES + T - 1) / T, T>>>(dst);
    dinv_kernel<<<(N_NODES + T - 1) / T, T>>>();
    scan_blocks<<<NBLK, 256>>>();
    scan_sums  <<<1, 512>>>();
    add_base   <<<NBLK, 256>>>();
    fill_kernel<<<(N_EDGES + T - 1) / T, T>>>(src, dst);

    const int G = (N_NODES * 16 + T - 1) / T;
    // k=1: gather from input feat, write featB, out = theta0*f + theta1*fnew
    agg_update_kernel<<<G, T>>>((const float4*)feat, (float4*)g_featB, out, -0.8f, 1, 1);
    // k=2: featB -> featA, out += theta2*fnew
    agg_update_kernel<<<G, T>>>((const float4*)g_featB, (float4*)g_featA, out, 0.4f, 0, 1);
    // k=3: featA -> (none), out += theta3*fnew
    agg_update_kernel<<<G, T>>>((const float4*)g_featA, nullptr, out, -0.1f, 0, 0);
}

// round 15
// speedup vs baseline: 13.0652x; 13.0652x over previous
#include <cuda_runtime.h>
#include <cstdint>

#define N_NODES 100000
#define N_EDGES 1200000
#define D_FEAT  64
#define CHUNKS  16              // 64 floats = 16 float4 per row

// THETA = (1.0, -0.8, 0.4, -0.1)
#define THETA0  1.0f
#define THETA1 -0.8f
#define THETA2  0.4f
#define THETA3 -0.1f

// ---------------- scratch (static device memory; no allocs allowed) --------
// RULES LEARNED:
//  (1) Explicitly zero all scratch each launch (harness pollutes memory).
//  (2) NEVER pass these symbols as kernel args from host code — the host-side
//      shadow address is a HOST pointer (ATS makes it "work" via NVLink-C2C,
//      silently wrong/slow). Reference them in device code only.
__device__ int   g_deg [N_NODES];
__device__ float g_dinv[N_NODES];
__device__ float g_feat[(size_t)N_NODES * D_FEAT];
__device__ float g_agg [(size_t)N_NODES * D_FEAT];

// ---------------- kernels ---------------------------------------------------

// Zero deg (0.4MB) and agg (25.6MB) in one pass. One float4 of agg per thread.
__global__ void zero_kernel() {
    int gid = blockIdx.x * blockDim.x + threadIdx.x;
    if (gid < N_NODES * CHUNKS) {
        ((float4*)g_agg)[gid] = make_float4(0.f, 0.f, 0.f, 0.f);
        if (gid < N_NODES) g_deg[gid] = 0;
    }
}

__global__ void deg_kernel(const int* __restrict__ dst) {
    int e = blockIdx.x * blockDim.x + threadIdx.x;
    if (e < N_EDGES) atomicAdd(&g_deg[__ldg(dst + e)], 1);
}

__global__ void dinv_kernel() {
    int v = blockIdx.x * blockDim.x + threadIdx.x;
    if (v < N_NODES) {
        float d = (float)g_deg[v];
        g_dinv[v] = rsqrtf(fmaxf(d, 1.0f));
    }
}

// Edge scatter: agg[dst] += fin[src] * dinv[src].
// fin = input feat (pass 1) or g_feat (resolved IN DEVICE CODE).
// 16 consecutive threads handle one edge (one float4 each) -> coalesced 256B
// row read; vectorized red.global.add.v4.f32 scatter (no return value).
__global__ void scatter_kernel(const float4* __restrict__ feat_in, int use_input,
                               const int* __restrict__ src,
                               const int* __restrict__ dst) {
    const float4* fin = use_input ? feat_in : (const float4*)g_feat;
    int gid = blockIdx.x * blockDim.x + threadIdx.x;
    if (gid >= N_EDGES * CHUNKS) return;
    int e = gid >> 4;
    int c = gid & 15;
    int s = __ldg(src + e);
    int d = __ldg(dst + e);
    float ds = __ldg(&g_dinv[s]);
    float4 f = __ldg(fin + s * CHUNKS + c);
    float mx = f.x * ds, my = f.y * ds, mz = f.z * ds, mw = f.w * ds;
    float* p = g_agg + (size_t)d * D_FEAT + c * 4;
    asm volatile("red.global.add.v4.f32 [%0], {%1, %2, %3, %4};"
                 :: "l"(p), "f"(mx), "f"(my), "f"(mz), "f"(mw)
                 : "memory");
}

// Node update:
//   fnew = fin - agg * dinv[v]
//   out  = first ? THETA0*fin + theta*fnew : out + theta*fnew
//   g_feat = fnew (unless last pass); agg = 0 (for next scatter / next replay)
__global__ void update_kernel(const float4* __restrict__ feat_in, int use_input,
                              float4* __restrict__ out,
                              float theta, int first, int write_feat) {
    const float4* fin = use_input ? feat_in : (const float4*)g_feat;
    int gid = blockIdx.x * blockDim.x + threadIdx.x;
    if (gid >= N_NODES * CHUNKS) return;
    int v = gid >> 4;
    float dv = __ldg(&g_dinv[v]);
    float4 a = ((float4*)g_agg)[gid];
    float4 f = fin[gid];
    float fx = f.x - a.x * dv;
    float fy = f.y - a.y * dv;
    float fz = f.z - a.z * dv;
    float fw = f.w - a.w * dv;

    if (write_feat) ((float4*)g_feat)[gid] = make_float4(fx, fy, fz, fw);
    ((float4*)g_agg)[gid] = make_float4(0.f, 0.f, 0.f, 0.f);

    if (first) {
        out[gid] = make_float4(THETA0 * f.x + theta * fx,
                               THETA0 * f.y + theta * fy,
                               THETA0 * f.z + theta * fz,
                               THETA0 * f.w + theta * fw);
    } else {
        float4 o = out[gid];
        out[gid] = make_float4(o.x + theta * fx, o.y + theta * fy,
                               o.z + theta * fz, o.w + theta * fw);
    }
}

// ---------------- launch -----------------------------------------------------

extern "C" void kernel_launch(void* const* d_in, const int* in_sizes, int n_in,
                              void* d_out, int out_size) {
    const float4* feat = (const float4*)d_in[0];
    const int*    src  = (const int*)d_in[1];
    const int*    dst  = (const int*)d_in[2];
    float4* out = (float4*)d_out;

    const int T = 256;
    const int node_elems = N_NODES * CHUNKS;   // 1.6M float4
    const int edge_elems = N_EDGES * CHUNKS;   // 19.2M threads
    const int GE = (edge_elems + T - 1) / T;
    const int GN = (node_elems + T - 1) / T;

    zero_kernel<<<GN, T>>>();                               // deg=0, agg=0
    deg_kernel <<<(N_EDGES + T - 1) / T, T>>>(dst);
    dinv_kernel<<<(N_NODES + T - 1) / T, T>>>();

    // k=1: gather directly from input feat; out = theta0*f + theta1*f1
    scatter_kernel<<<GE, T>>>(feat, 1, src, dst);
    update_kernel <<<GN, T>>>(feat, 1, out, THETA1, 1, 1);
    // k=2: g_feat -> g_feat
    scatter_kernel<<<GE, T>>>(feat, 0, src, dst);
    update_kernel <<<GN, T>>>(feat, 0, out, THETA2, 0, 1);
    // k=3: no feat write needed
    scatter_kernel<<<GE, T>>>(feat, 0, src, dst);
    update_kernel <<<GN, T>>>(feat, 0, out, THETA3, 0, 0);
}